// round 3
// baseline (speedup 1.0000x reference)
#include <cuda_runtime.h>

#define B_   8
#define S_   32
#define D_   256
#define M_   2048
#define GPB  16      // blocks per batch
#define RPB  128     // rows per block
#define NT   256     // threads per block
#define PSTRIDE 272  // floats per partial record
#define NEGINF (__int_as_float(0xff800000))

// ----------------------------- device state -----------------------------
__device__ float g_mem [B_*M_*D_];      // 16 MB working memory
__device__ float g_tmpq[B_*S_*D_];      // x@Wq + bq
__device__ float g_qt  [B_*S_*D_];      // (x@Wq+bq)@Wk^T / sqrt(D)
__device__ float g_xg  [B_*S_*D_];      // x@Wg1 + bg
__device__ float g_bgc [D_];            // bv@Wg2
__device__ float g_C   [D_*D_];         // Wv@Wg2
__device__ float g_part[B_*GPB*PSTRIDE];// per-block partials
__device__ int   g_tidx[B_*GPB*8];      // per-block top8 indices (global row ids)
__device__ float g_gv  [B_*D_];         // gate vector per batch
__device__ int   g_cnt [2*B_*S_];       // barrier counters (A then B)

__device__ __forceinline__ int ldacq(const int* p) {
    int v;
    asm volatile("ld.acquire.gpu.global.b32 %0, [%1];" : "=r"(v) : "l"(p) : "memory");
    return v;
}

// ----------------------------- init kernel 1 -----------------------------
// roles by blockIdx.x:
//   [0,512)    : replicate memory -> g_mem (B copies)
//   [512,544)  : g_tmpq = x@Wq + bq        (8 rows / block)
//   [544,576)  : g_xg   = x@Wg1 + bg       (8 rows / block)
//   [576,608)  : g_C    = Wv@Wg2           (8 k-rows / block)
//   608        : zero counters + g_bgc = bv@Wg2
__global__ void mal_init1(const float* __restrict__ x, const float* __restrict__ memory,
                          const float* __restrict__ Wq, const float* __restrict__ bq,
                          const float* __restrict__ Wg, const float* __restrict__ bg,
                          const float* __restrict__ Wv, const float* __restrict__ bv)
{
    __shared__ float s_buf[2048];
    const int bid = blockIdx.x, tid = threadIdx.x;

    if (bid < 512) {
        const float4* src = (const float4*)memory;
        float4* dst = (float4*)g_mem;
        int base = bid * 2048 + tid;
        #pragma unroll
        for (int i = 0; i < 8; ++i) {
            int j = base + i * NT;
            dst[j] = src[j & (M_*D_/4 - 1)];
        }
    } else if (bid < 544) {
        int r0 = (bid - 512) * 8;
        for (int i = tid; i < 2048; i += NT) s_buf[i] = x[r0*D_ + i];
        __syncthreads();
        float acc[8];
        #pragma unroll
        for (int r = 0; r < 8; ++r) acc[r] = 0.f;
        for (int j = 0; j < D_; ++j) {
            float w = Wq[j*D_ + tid];
            #pragma unroll
            for (int r = 0; r < 8; ++r) acc[r] += s_buf[r*D_ + j] * w;
        }
        float bb = bq[tid];
        #pragma unroll
        for (int r = 0; r < 8; ++r) g_tmpq[(r0+r)*D_ + tid] = acc[r] + bb;
    } else if (bid < 576) {
        int r0 = (bid - 544) * 8;
        for (int i = tid; i < 2048; i += NT) s_buf[i] = x[r0*D_ + i];
        __syncthreads();
        float acc[8];
        #pragma unroll
        for (int r = 0; r < 8; ++r) acc[r] = 0.f;
        for (int j = 0; j < D_; ++j) {
            float w = Wg[j*D_ + tid];
            #pragma unroll
            for (int r = 0; r < 8; ++r) acc[r] += s_buf[r*D_ + j] * w;
        }
        float bb = bg[tid];
        #pragma unroll
        for (int r = 0; r < 8; ++r) g_xg[(r0+r)*D_ + tid] = acc[r] + bb;
    } else if (bid < 608) {
        int k0 = (bid - 576) * 8;
        for (int i = tid; i < 2048; i += NT) s_buf[i] = Wv[k0*D_ + i];
        __syncthreads();
        float acc[8];
        #pragma unroll
        for (int r = 0; r < 8; ++r) acc[r] = 0.f;
        for (int j = 0; j < D_; ++j) {
            float w = Wg[(D_ + j)*D_ + tid];
            #pragma unroll
            for (int r = 0; r < 8; ++r) acc[r] += s_buf[r*D_ + j] * w;
        }
        #pragma unroll
        for (int r = 0; r < 8; ++r) g_C[(k0+r)*D_ + tid] = acc[r];
    } else {
        g_cnt[tid]      = 0;
        g_cnt[NT + tid] = 0;
        float acc = 0.f;
        for (int j = 0; j < D_; ++j) acc += bv[j] * Wg[(D_ + j)*D_ + tid];
        g_bgc[tid] = acc;
    }
}

// ----------------------------- init kernel 2 -----------------------------
// g_qt[bt,d] = (1/sqrt(D)) * sum_k g_tmpq[bt,k] * Wk[d,k]
__global__ void mal_init2(const float* __restrict__ Wk)
{
    __shared__ float s_buf[2048];
    const int bid = blockIdx.x, tid = threadIdx.x;
    const int r0 = bid * 8;
    for (int i = tid; i < 2048; i += NT) s_buf[i] = g_tmpq[r0*D_ + i];
    __syncthreads();
    float acc[8];
    #pragma unroll
    for (int r = 0; r < 8; ++r) acc[r] = 0.f;
    const float4* wrow = (const float4*)(Wk + tid * D_);
    for (int k4 = 0; k4 < 64; ++k4) {
        float4 w = wrow[k4];
        #pragma unroll
        for (int r = 0; r < 8; ++r) {
            const float* tptr = s_buf + r*D_ + k4*4;
            acc[r] += tptr[0]*w.x + tptr[1]*w.y + tptr[2]*w.z + tptr[3]*w.w;
        }
    }
    #pragma unroll
    for (int r = 0; r < 8; ++r) g_qt[(r0+r)*D_ + tid] = acc[r] * 0.0625f;
}

// ----------------------------- top-8 selection -----------------------------
// selects top-8 of 128 (value desc, tie -> lower stored index) from s_cv/s_ci.
// all 256 threads must call (contains __syncthreads).
__device__ __forceinline__ void top8_select(float* s_cv, int* s_ci,
                                            float* s_rv, int* s_rc, int* s_rs,
                                            float* s_selv, int* s_sel, int tid)
{
    const int lane = tid & 31, warp = tid >> 5;
    for (int k = 0; k < 8; ++k) {
        float v  = (tid < 128) ? s_cv[tid] : NEGINF;
        int   ci = (tid < 128) ? s_ci[tid] : 0x7fffffff;
        int slot = tid;
        #pragma unroll
        for (int o = 16; o; o >>= 1) {
            float ov = __shfl_xor_sync(0xffffffffu, v, o);
            int   oc = __shfl_xor_sync(0xffffffffu, ci, o);
            int   os = __shfl_xor_sync(0xffffffffu, slot, o);
            if (ov > v || (ov == v && oc < ci)) { v = ov; ci = oc; slot = os; }
        }
        if (lane == 0) { s_rv[warp] = v; s_rc[warp] = ci; s_rs[warp] = slot; }
        __syncthreads();
        if (tid == 0) {
            float bvv = s_rv[0]; int bc = s_rc[0], bs = s_rs[0];
            #pragma unroll
            for (int w = 1; w < 4; ++w) {
                if (s_rv[w] > bvv || (s_rv[w] == bvv && s_rc[w] < bc)) {
                    bvv = s_rv[w]; bc = s_rc[w]; bs = s_rs[w];
                }
            }
            s_selv[k] = bvv; s_sel[k] = bc; s_cv[bs] = NEGINF;
        }
        __syncthreads();
    }
}

// ----------------------------- main persistent kernel -----------------------------
__global__ void __launch_bounds__(NT, 1)
mal_main(const float* __restrict__ x, const float* __restrict__ Wv,
         const float* __restrict__ bv, float* __restrict__ out)
{
    __shared__ float s_q[D_];
    __shared__ float s_wacc[8][D_];
    __shared__ float s_wm[8], s_ws[8];
    __shared__ float s_cv[128];
    __shared__ int   s_ci[128];
    __shared__ float s_rv[8];
    __shared__ int   s_rc[8], s_rs[8];
    __shared__ float s_selv[8];
    __shared__ int   s_sel[8];
    __shared__ float s_p[D_];
    __shared__ float s_red[NT];
    __shared__ float s_pm[16], s_scale[16];
    __shared__ float s_bm, s_invS;

    const int tid  = threadIdx.x, lane = tid & 31, warp = tid >> 5;
    const int b    = blockIdx.x >> 4;
    const int blk  = blockIdx.x & 15;
    float* part    = g_part + blockIdx.x * PSTRIDE;
    int* cA        = g_cnt + b * S_;
    int* cB        = g_cnt + NT + b * S_;
    const int d0   = lane * 4;
    const int d1   = 128 + lane * 4;

    for (int t = 0; t < S_; ++t) {
        // ---- apply previous step's gated top-8 updates to owned rows ----
        if (t > 0) {
            bool ownany = false;
            #pragma unroll
            for (int k = 0; k < 8; ++k) if ((s_sel[k] >> 7) == blk) ownany = true;
            if (ownany) {
                float gd   = __ldcg(&g_gv[b*D_ + tid]);
                float xd   = __ldg(&x[(b*S_ + (t-1))*D_ + tid]);
                float keep = 1.0f - gd, add = gd * xd;
                #pragma unroll
                for (int k = 0; k < 8; ++k) {
                    int gi = s_sel[k];
                    if ((gi >> 7) == blk) {
                        float* row = g_mem + (b*M_ + gi)*D_;
                        row[tid] = keep * row[tid] + add;
                    }
                }
            }
        }
        s_q[tid] = g_qt[(b*S_ + t)*D_ + tid];
        __syncthreads();

        // ---- phase A: stream own 128 rows, online softmax + weighted sum ----
        const float q0 = s_q[d0],   q1 = s_q[d0+1], q2 = s_q[d0+2], q3 = s_q[d0+3];
        const float q4 = s_q[d1],   q5 = s_q[d1+1], q6 = s_q[d1+2], q7 = s_q[d1+3];
        const float* baseRow = g_mem + (b*M_ + blk*RPB + warp*16)*D_;
        float mw = NEGINF, sw = 0.f;
        float a0=0,a1=0,a2=0,a3=0,a4=0,a5=0,a6=0,a7=0;
        #pragma unroll 4
        for (int r = 0; r < 16; ++r) {
            float4 va = *(const float4*)(baseRow + r*D_ + d0);
            float4 vb = *(const float4*)(baseRow + r*D_ + d1);
            float dt = va.x*q0 + va.y*q1 + va.z*q2 + va.w*q3
                     + vb.x*q4 + vb.y*q5 + vb.z*q6 + vb.w*q7;
            #pragma unroll
            for (int o = 16; o; o >>= 1) dt += __shfl_xor_sync(0xffffffffu, dt, o);
            if (lane == 0) s_cv[warp*16 + r] = dt;
            float e;
            if (dt > mw) {
                float f = __expf(mw - dt);
                sw *= f; a0*=f; a1*=f; a2*=f; a3*=f; a4*=f; a5*=f; a6*=f; a7*=f;
                mw = dt; e = 1.0f;
            } else {
                e = __expf(dt - mw);
            }
            sw += e;
            a0 += e*va.x; a1 += e*va.y; a2 += e*va.z; a3 += e*va.w;
            a4 += e*vb.x; a5 += e*vb.y; a6 += e*vb.z; a7 += e*vb.w;
        }
        if (lane == 0) { s_wm[warp] = mw; s_ws[warp] = sw; }
        s_wacc[warp][d0]   = a0; s_wacc[warp][d0+1] = a1;
        s_wacc[warp][d0+2] = a2; s_wacc[warp][d0+3] = a3;
        s_wacc[warp][d1]   = a4; s_wacc[warp][d1+1] = a5;
        s_wacc[warp][d1+2] = a6; s_wacc[warp][d1+3] = a7;
        if (tid < 128) s_ci[tid] = blk*RPB + tid;
        __syncthreads();

        if (tid == 0) {
            float bm = s_wm[0];
            #pragma unroll
            for (int w = 1; w < 8; ++w) bm = fmaxf(bm, s_wm[w]);
            s_bm = bm;
        }
        __syncthreads();
        {
            float bm = s_bm;
            float pv = 0.f;
            #pragma unroll
            for (int w = 0; w < 8; ++w) pv += s_wacc[w][tid] * __expf(s_wm[w] - bm);
            part[2 + tid] = pv;
            if (tid == 0) {
                float bs = 0.f;
                #pragma unroll
                for (int w = 0; w < 8; ++w) bs += s_ws[w] * __expf(s_wm[w] - bm);
                part[0] = bm; part[1] = bs;
            }
        }
        // local top-8 (s_cv holds the 128 logits, s_ci global row ids)
        top8_select(s_cv, s_ci, s_rv, s_rc, s_rs, s_selv, s_sel, tid);
        if (tid < 8) {
            part[258 + tid] = s_selv[tid];
            g_tidx[blockIdx.x*8 + tid] = s_sel[tid];
        }
        __threadfence();
        __syncthreads();
        if (tid == 0) {
            atomicAdd(&cA[t], 1);
            while (ldacq(&cA[t]) < GPB) { }
        }
        __syncthreads();

        // ---- merge 16 partials (every block, redundantly) ----
        if (tid < 16) s_pm[tid] = __ldcg(&g_part[(b*GPB + tid)*PSTRIDE]);
        __syncthreads();
        if (tid == 0) {
            float Mx = s_pm[0];
            #pragma unroll
            for (int i = 1; i < 16; ++i) Mx = fmaxf(Mx, s_pm[i]);
            float Ssum = 0.f;
            #pragma unroll
            for (int i = 0; i < 16; ++i) {
                float sc = __expf(s_pm[i] - Mx);
                s_scale[i] = sc;
                Ssum += sc * __ldcg(&g_part[(b*GPB + i)*PSTRIDE + 1]);
            }
            s_invS = 1.0f / Ssum;
        }
        __syncthreads();
        {
            float pv = 0.f;
            #pragma unroll
            for (int i = 0; i < 16; ++i)
                pv += __ldcg(&g_part[(b*GPB + i)*PSTRIDE + 2 + tid]) * s_scale[i];
            s_p[tid] = pv * s_invS;
        }
        if (tid < 128) {
            int i = tid >> 3, j = tid & 7;
            s_cv[tid] = __ldcg(&g_part[(b*GPB + i)*PSTRIDE + 258 + j]);
            s_ci[tid] = __ldcg(&g_tidx[(b*GPB + i)*8 + j]);
        }
        __syncthreads();
        // global top-8 -> s_sel (used for updates at t+1)
        top8_select(s_cv, s_ci, s_rv, s_rc, s_rs, s_selv, s_sel, tid);

        // ---- slice GEMV: out[dbase..+16) and g[dbase..+16) from p ----
        {
            const int dbase = blk * 16;
            const float* Mp = (lane < 16) ? (Wv + dbase + lane)
                                          : (g_C + dbase + (lane - 16));
            float acc = 0.f;
            const int k0 = warp * 32;
            #pragma unroll 8
            for (int kk = 0; kk < 32; ++kk)
                acc += s_p[k0 + kk] * Mp[(k0 + kk)*D_];
            s_red[tid] = acc;
        }
        __syncthreads();
        if (tid < 32) {
            float tot = 0.f;
            #pragma unroll
            for (int w = 0; w < 8; ++w) tot += s_red[w*32 + tid];
            const int dbase = blk * 16;
            if (tid < 16) {
                out[(b*S_ + t)*D_ + dbase + tid] = tot + __ldg(&bv[dbase + tid]);
            } else {
                int d = dbase + tid - 16;
                float z = g_xg[(b*S_ + t)*D_ + d] + g_bgc[d] + tot;
                g_gv[b*D_ + d] = 1.0f / (1.0f + __expf(-z));
            }
        }
        __threadfence();
        __syncthreads();
        if (tid == 0) {
            atomicAdd(&cB[t], 1);
            while (ldacq(&cB[t]) < GPB) { }
        }
        __syncthreads();
    }
}

// ----------------------------- launch -----------------------------
extern "C" void kernel_launch(void* const* d_in, const int* in_sizes, int n_in,
                              void* d_out, int out_size)
{
    const float* x      = (const float*)d_in[0];
    const float* memory = (const float*)d_in[1];
    const float* Wq     = (const float*)d_in[2];
    const float* bq     = (const float*)d_in[3];
    const float* Wk     = (const float*)d_in[4];
    // d_in[5] = bk : provably unused (constant logit shift; softmax/top-k invariant)
    const float* Wv     = (const float*)d_in[6];
    const float* bv     = (const float*)d_in[7];
    const float* Wg     = (const float*)d_in[8];
    const float* bg     = (const float*)d_in[9];
    float* out = (float*)d_out;

    mal_init1<<<609, NT>>>(x, memory, Wq, bq, Wg, bg, Wv, bv);
    mal_init2<<<32, NT>>>(Wk);
    mal_main<<<B_*GPB, NT>>>(x, Wv, bv, out);
}

// round 4
// speedup vs baseline: 1.4530x; 1.4530x over previous
#include <cuda_runtime.h>

#define B_   8
#define S_   32
#define D_   256
#define M_   2048
#define GPB  16      // blocks per batch
#define RPB  128     // rows per block
#define NT   256     // threads per block
#define PST  272     // floats per partial record
#define NEGINF (__int_as_float(0xff800000))

// ----------------------------- device state -----------------------------
__device__ float g_mem [B_*M_*D_];        // 16 MB working memory
__device__ float g_tmpq[B_*S_*D_];        // x@Wq + bq
__device__ float g_qt  [B_*S_*D_];        // (x@Wq+bq)@Wk^T / sqrt(D)
__device__ float g_xg  [B_*S_*D_];        // x@Wg1 + bg
__device__ float g_bgc [D_];              // bv@Wg2
__device__ float g_C   [D_*D_];           // Wv@Wg2
__device__ float g_part[2*B_*GPB*PST];    // per-block partials (double buffered)
__device__ int   g_tidx[2*B_*GPB*8];      // per-block top8 global row ids
__device__ float g_gv  [B_*D_];           // gate vector per batch
__device__ int   g_cnt [2*B_*S_];         // barrier counters (A then B)

__device__ __forceinline__ int ldacq(const int* p) {
    int v;
    asm volatile("ld.acquire.gpu.global.b32 %0, [%1];" : "=r"(v) : "l"(p) : "memory");
    return v;
}

// ----------------------------- init kernel 1 -----------------------------
// roles by blockIdx.x:
//   [0,512)    : replicate memory -> g_mem (B copies)
//   [512,544)  : g_tmpq = x@Wq + bq        (8 rows / block)
//   [544,576)  : g_xg   = x@Wg1 + bg       (8 rows / block)
//   [576,608)  : g_C    = Wv@Wg2           (8 k-rows / block)
//   608        : zero counters + g_bgc = bv@Wg2
__global__ void mal_init1(const float* __restrict__ x, const float* __restrict__ memory,
                          const float* __restrict__ Wq, const float* __restrict__ bq,
                          const float* __restrict__ Wg, const float* __restrict__ bg,
                          const float* __restrict__ Wv, const float* __restrict__ bv)
{
    __shared__ float s_buf[2048];
    const int bid = blockIdx.x, tid = threadIdx.x;

    if (bid < 512) {
        const float4* src = (const float4*)memory;
        float4* dst = (float4*)g_mem;
        int base = bid * 2048 + tid;
        #pragma unroll
        for (int i = 0; i < 8; ++i) {
            int j = base + i * NT;
            dst[j] = src[j & (M_*D_/4 - 1)];
        }
    } else if (bid < 544) {
        int r0 = (bid - 512) * 8;
        for (int i = tid; i < 2048; i += NT) s_buf[i] = x[r0*D_ + i];
        __syncthreads();
        float acc[8];
        #pragma unroll
        for (int r = 0; r < 8; ++r) acc[r] = 0.f;
        #pragma unroll 8
        for (int j = 0; j < D_; ++j) {
            float w = Wq[j*D_ + tid];
            #pragma unroll
            for (int r = 0; r < 8; ++r) acc[r] += s_buf[r*D_ + j] * w;
        }
        float bb = bq[tid];
        #pragma unroll
        for (int r = 0; r < 8; ++r) g_tmpq[(r0+r)*D_ + tid] = acc[r] + bb;
    } else if (bid < 576) {
        int r0 = (bid - 544) * 8;
        for (int i = tid; i < 2048; i += NT) s_buf[i] = x[r0*D_ + i];
        __syncthreads();
        float acc[8];
        #pragma unroll
        for (int r = 0; r < 8; ++r) acc[r] = 0.f;
        #pragma unroll 8
        for (int j = 0; j < D_; ++j) {
            float w = Wg[j*D_ + tid];
            #pragma unroll
            for (int r = 0; r < 8; ++r) acc[r] += s_buf[r*D_ + j] * w;
        }
        float bb = bg[tid];
        #pragma unroll
        for (int r = 0; r < 8; ++r) g_xg[(r0+r)*D_ + tid] = acc[r] + bb;
    } else if (bid < 608) {
        int k0 = (bid - 576) * 8;
        for (int i = tid; i < 2048; i += NT) s_buf[i] = Wv[k0*D_ + i];
        __syncthreads();
        float acc[8];
        #pragma unroll
        for (int r = 0; r < 8; ++r) acc[r] = 0.f;
        #pragma unroll 8
        for (int j = 0; j < D_; ++j) {
            float w = Wg[(D_ + j)*D_ + tid];
            #pragma unroll
            for (int r = 0; r < 8; ++r) acc[r] += s_buf[r*D_ + j] * w;
        }
        #pragma unroll
        for (int r = 0; r < 8; ++r) g_C[(k0+r)*D_ + tid] = acc[r];
    } else {
        g_cnt[tid]      = 0;
        g_cnt[NT + tid] = 0;
        float acc = 0.f;
        #pragma unroll 8
        for (int j = 0; j < D_; ++j) acc += bv[j] * Wg[(D_ + j)*D_ + tid];
        g_bgc[tid] = acc;
    }
}

// ----------------------------- init kernel 2 -----------------------------
// g_qt[bt,d] = (1/sqrt(D)) * sum_k g_tmpq[bt,k] * Wk[d,k]
// warp-coalesced: each warp handles 32 d-rows; lanes split k-dim.
__global__ void mal_init2(const float* __restrict__ Wk)
{
    __shared__ float s_t[8 * D_];
    const int bid = blockIdx.x, tid = threadIdx.x;
    const int lane = tid & 31, warp = tid >> 5;
    const int r0 = bid * 8;
    for (int i = tid; i < 2048; i += NT) s_t[i] = g_tmpq[r0*D_ + i];
    __syncthreads();

    for (int dd = 0; dd < 32; ++dd) {
        int d = warp * 32 + dd;
        float4 w0 = *(const float4*)(Wk + d*D_ + lane*4);
        float4 w1 = *(const float4*)(Wk + d*D_ + 128 + lane*4);
        float dt[8];
        #pragma unroll
        for (int r = 0; r < 8; ++r) {
            float4 t0 = *(const float4*)(s_t + r*D_ + lane*4);
            float4 t1 = *(const float4*)(s_t + r*D_ + 128 + lane*4);
            dt[r] = t0.x*w0.x + t0.y*w0.y + t0.z*w0.z + t0.w*w0.w
                  + t1.x*w1.x + t1.y*w1.y + t1.z*w1.z + t1.w*w1.w;
        }
        #pragma unroll
        for (int r = 0; r < 8; ++r) {
            #pragma unroll
            for (int o = 16; o; o >>= 1) dt[r] += __shfl_xor_sync(0xffffffffu, dt[r], o);
        }
        if (lane == 0) {
            #pragma unroll
            for (int r = 0; r < 8; ++r) g_qt[(r0+r)*D_ + d] = dt[r] * 0.0625f;
        }
    }
}

// ----------------------------- main persistent kernel -----------------------------
__global__ void __launch_bounds__(NT, 1)
mal_main(const float* __restrict__ x, const float* __restrict__ Wv,
         const float* __restrict__ bv, float* __restrict__ out)
{
    __shared__ float s_q[D_];
    __shared__ float s_wacc[8][D_];
    __shared__ float s_lg[128];       // 128 raw logits
    __shared__ float s_e[128];        // exp(logit - block max)
    __shared__ float s_r8[8];
    __shared__ float s_cv[128];
    __shared__ int   s_ci[128];
    __shared__ int   s_sel[8];        // global top-8 row ids (persists across steps)
    __shared__ float s_p[D_];
    __shared__ float s_red[NT];
    __shared__ float s_scale[16];
    __shared__ float s_bm, s_invS;

    const int tid  = threadIdx.x, lane = tid & 31, warp = tid >> 5;
    const int b    = blockIdx.x >> 4;
    const int blk  = blockIdx.x & 15;
    int* cA        = g_cnt + b * S_;
    int* cB        = g_cnt + NT + b * S_;
    const int d0   = lane * 4;
    const int d1   = 128 + lane * 4;
    const float* baseRow = g_mem + (b*M_ + blk*RPB + warp*16)*D_;

    for (int t = 0; t < S_; ++t) {
        const int buf  = t & 1;
        float* part    = g_part + buf*(B_*GPB*PST) + blockIdx.x * PST;
        int*   tidx    = g_tidx + buf*(B_*GPB*8);

        // ---- apply previous step's gated top-8 updates to owned rows ----
        if (t > 0) {
            bool ownany = false;
            #pragma unroll
            for (int k = 0; k < 8; ++k) if ((s_sel[k] >> 7) == blk) ownany = true;
            if (ownany) {
                if (tid == 0) { while (ldacq(&cB[t-1]) < GPB) { } }
                __syncthreads();
                float gd   = __ldcg(&g_gv[b*D_ + tid]);
                float xd   = __ldg(&x[(b*S_ + (t-1))*D_ + tid]);
                float keep = 1.0f - gd, add = gd * xd;
                #pragma unroll
                for (int k = 0; k < 8; ++k) {
                    int gi = s_sel[k];
                    if ((gi >> 7) == blk) {
                        float* row = g_mem + (b*M_ + gi)*D_;
                        row[tid] = keep * row[tid] + add;
                    }
                }
            }
        }
        s_q[tid] = g_qt[(b*S_ + t)*D_ + tid];
        __syncthreads();

        // ---- pass 1: load own 128 rows into regs, compute all logits ----
        const float q0 = s_q[d0],   q1 = s_q[d0+1], q2 = s_q[d0+2], q3 = s_q[d0+3];
        const float q4 = s_q[d1],   q5 = s_q[d1+1], q6 = s_q[d1+2], q7 = s_q[d1+3];
        float4 ra[16], rb[16];
        #pragma unroll
        for (int r = 0; r < 16; ++r) {
            ra[r] = *(const float4*)(baseRow + r*D_ + d0);
            rb[r] = *(const float4*)(baseRow + r*D_ + d1);
            float dt = ra[r].x*q0 + ra[r].y*q1 + ra[r].z*q2 + ra[r].w*q3
                     + rb[r].x*q4 + rb[r].y*q5 + rb[r].z*q6 + rb[r].w*q7;
            #pragma unroll
            for (int o = 16; o; o >>= 1) dt += __shfl_xor_sync(0xffffffffu, dt, o);
            if (lane == 0) s_lg[warp*16 + r] = dt;
        }
        __syncthreads();

        // ---- block max, exp table, block sum ----
        float v = (tid < 128) ? s_lg[tid] : NEGINF;
        {
            float m = v;
            #pragma unroll
            for (int o = 16; o; o >>= 1) m = fmaxf(m, __shfl_xor_sync(0xffffffffu, m, o));
            if (lane == 0) s_r8[warp] = m;
        }
        __syncthreads();
        if (tid == 0) {
            float bm = s_r8[0];
            #pragma unroll
            for (int w = 1; w < 8; ++w) bm = fmaxf(bm, s_r8[w]);
            s_bm = bm;
        }
        __syncthreads();
        const float bm = s_bm;
        float e = (tid < 128) ? __expf(v - bm) : 0.f;
        if (tid < 128) s_e[tid] = e;
        {
            float se = e;
            #pragma unroll
            for (int o = 16; o; o >>= 1) se += __shfl_xor_sync(0xffffffffu, se, o);
            if (lane == 0) s_r8[warp] = se;
        }
        __syncthreads();

        // ---- pass 2: weighted row sum from registers ----
        {
            float4 A = {0,0,0,0}, Bb = {0,0,0,0};
            #pragma unroll
            for (int r = 0; r < 16; ++r) {
                float er = s_e[warp*16 + r];
                A.x += er*ra[r].x; A.y += er*ra[r].y; A.z += er*ra[r].z; A.w += er*ra[r].w;
                Bb.x += er*rb[r].x; Bb.y += er*rb[r].y; Bb.z += er*rb[r].z; Bb.w += er*rb[r].w;
            }
            *(float4*)&s_wacc[warp][d0] = A;
            *(float4*)&s_wacc[warp][d1] = Bb;
        }
        __syncthreads();
        {
            float pv = 0.f;
            #pragma unroll
            for (int w = 0; w < 8; ++w) pv += s_wacc[w][tid];
            part[2 + tid] = pv;
            if (tid == 0) {
                float sw = 0.f;
                #pragma unroll
                for (int w = 0; w < 8; ++w) sw += s_r8[w];
                part[0] = bm; part[1] = sw;
            }
        }
        // ---- local top-8 by rank (tie -> lower index) ----
        if (tid < 128) {
            float vv = s_lg[tid];
            int rk = 0;
            #pragma unroll 8
            for (int j = 0; j < 128; ++j) {
                float u = s_lg[j];
                rk += (u > vv) || (u == vv && j < tid);
            }
            if (rk < 8) {
                part[258 + rk] = vv;
                tidx[blockIdx.x*8 + rk] = blk*RPB + tid;
            }
        }
        __threadfence();
        __syncthreads();
        if (tid == 0) {
            atomicAdd(&cA[t], 1);
            while (ldacq(&cA[t]) < GPB) { }
        }
        __syncthreads();

        // ---- merge 16 partials (redundant per block) ----
        if (warp == 0) {
            float bmv = (lane < 16) ? __ldcg(&g_part[buf*(B_*GPB*PST) + (b*GPB + lane)*PST])     : NEGINF;
            float swv = (lane < 16) ? __ldcg(&g_part[buf*(B_*GPB*PST) + (b*GPB + lane)*PST + 1]) : 0.f;
            float Mx = bmv;
            #pragma unroll
            for (int o = 16; o; o >>= 1) Mx = fmaxf(Mx, __shfl_xor_sync(0xffffffffu, Mx, o));
            float sc = (lane < 16) ? __expf(bmv - Mx) : 0.f;
            if (lane < 16) s_scale[lane] = sc;
            float Ssum = sc * swv;
            #pragma unroll
            for (int o = 16; o; o >>= 1) Ssum += __shfl_xor_sync(0xffffffffu, Ssum, o);
            if (lane == 0) s_invS = 1.0f / Ssum;
        }
        if (tid >= 128 && tid < 256) {
            int ii = tid - 128;
            int i = ii >> 3, j = ii & 7;
            s_cv[ii] = __ldcg(&g_part[buf*(B_*GPB*PST) + (b*GPB + i)*PST + 258 + j]);
            s_ci[ii] = __ldcg(&g_tidx[buf*(B_*GPB*8) + (b*GPB + i)*8 + j]);
        }
        __syncthreads();
        {
            float pv = 0.f;
            #pragma unroll
            for (int i = 0; i < 16; ++i)
                pv += __ldcg(&g_part[buf*(B_*GPB*PST) + (b*GPB + i)*PST + 2 + tid]) * s_scale[i];
            s_p[tid] = pv * s_invS;
        }
        // ---- global top-8 by rank over 128 candidates ----
        if (tid < 128) {
            float vv = s_cv[tid];
            int   ix = s_ci[tid];
            int rk = 0;
            #pragma unroll 8
            for (int j = 0; j < 128; ++j) {
                float u = s_cv[j];
                int  ui = s_ci[j];
                rk += (u > vv) || (u == vv && ui < ix);
            }
            if (rk < 8) s_sel[rk] = ix;
        }
        __syncthreads();

        // ---- slice GEMV: out[dbase..+16) and gate[dbase..+16) from p ----
        {
            const int dbase = blk * 16;
            const float* Mp = (lane < 16) ? (Wv + dbase + lane)
                                          : (g_C + dbase + (lane - 16));
            float acc = 0.f;
            const int k0 = warp * 32;
            #pragma unroll
            for (int kk = 0; kk < 32; ++kk)
                acc += s_p[k0 + kk] * Mp[(k0 + kk)*D_];
            s_red[tid] = acc;
        }
        __syncthreads();
        if (tid < 32) {
            float tot = 0.f;
            #pragma unroll
            for (int w = 0; w < 8; ++w) tot += s_red[w*32 + tid];
            const int dbase = blk * 16;
            if (tid < 16) {
                out[(b*S_ + t)*D_ + dbase + tid] = tot + __ldg(&bv[dbase + tid]);
            } else {
                int d = dbase + tid - 16;
                float z = g_xg[(b*S_ + t)*D_ + d] + g_bgc[d] + tot;
                g_gv[b*D_ + d] = 1.0f / (1.0f + __expf(-z));
            }
        }
        __threadfence();
        __syncthreads();
        if (tid == 0) atomicAdd(&cB[t], 1);   // no wait here: owners wait at t+1
        __syncthreads();
    }
}

// ----------------------------- launch -----------------------------
extern "C" void kernel_launch(void* const* d_in, const int* in_sizes, int n_in,
                              void* d_out, int out_size)
{
    const float* x      = (const float*)d_in[0];
    const float* memory = (const float*)d_in[1];
    const float* Wq     = (const float*)d_in[2];
    const float* bq     = (const float*)d_in[3];
    const float* Wk     = (const float*)d_in[4];
    // d_in[5] = bk : constant logit shift; softmax/top-k invariant -> unused
    const float* Wv     = (const float*)d_in[6];
    const float* bv     = (const float*)d_in[7];
    const float* Wg     = (const float*)d_in[8];
    const float* bg     = (const float*)d_in[9];
    float* out = (float*)d_out;

    mal_init1<<<609, NT>>>(x, memory, Wq, bq, Wg, bg, Wv, bv);
    mal_init2<<<32, NT>>>(Wk);
    mal_main<<<B_*GPB, NT>>>(x, Wv, bv, out);
}

// round 5
// speedup vs baseline: 1.6419x; 1.1300x over previous
#include <cuda_runtime.h>

#define B_   8
#define S_   32
#define D_   256
#define M_   2048
#define GPB  16      // blocks per batch
#define RPB  128     // rows per block
#define NT   256     // threads per block
#define PST  272     // floats per partial record
#define NEGINF (__int_as_float(0xff800000))

// ----------------------------- device state -----------------------------
__device__ float g_mem [B_*M_*D_];        // 16 MB working memory
__device__ float g_tmpq[B_*S_*D_];        // x@Wq + bq
__device__ float g_qt  [B_*S_*D_];        // (x@Wq+bq)@Wk^T / sqrt(D)
__device__ float g_xg  [B_*S_*D_];        // x@Wg1 + bg
__device__ float g_bgc [D_];              // bv@Wg2
__device__ float g_C   [D_*D_];           // Wv@Wg2
__device__ float g_part[2*B_*GPB*PST];    // per-block partials (double buffered)
__device__ int   g_tidx[2*B_*GPB*8];      // per-block top8 global row ids
__device__ float g_gv  [B_*D_];           // gate vector per batch
__device__ int   g_cnt [2*B_*S_];         // barrier counters (A then B)

__device__ __forceinline__ int ldacq(const int* p) {
    int v;
    asm volatile("ld.acquire.gpu.global.b32 %0, [%1];" : "=r"(v) : "l"(p) : "memory");
    return v;
}
// release-arrive: orders ALL prior writes of the CTA (via preceding bar.sync)
// before the counter increment, WITHOUT the L1D-flushing CCTL.IVALL that
// __threadfence() emits on sm_103a.
__device__ __forceinline__ void red_release(int* p) {
    asm volatile("red.release.gpu.global.add.s32 [%0], %1;" :: "l"(p), "r"(1) : "memory");
}

// ----------------------------- init kernel 1 -----------------------------
// roles by blockIdx.x (GEMV blocks first so they start in wave 0):
//   [0,32)     : g_tmpq = x@Wq + bq   (8 rows / block)
//   [32,64)    : g_xg   = x@Wg1 + bg
//   [64,96)    : g_C    = Wv@Wg2
//   96         : counters + g_bgc = bv@Wg2
//   [97,1121)  : replicate memory -> g_mem (B copies), 16KB/block
__global__ void mal_init1(const float* __restrict__ x, const float* __restrict__ memory,
                          const float* __restrict__ Wq, const float* __restrict__ bq,
                          const float* __restrict__ Wg, const float* __restrict__ bg,
                          const float* __restrict__ Wv, const float* __restrict__ bv)
{
    __shared__ float s_buf[2048];
    const int bid = blockIdx.x, tid = threadIdx.x;

    if (bid >= 97) {
        const float4* src = (const float4*)memory;
        float4* dst = (float4*)g_mem;
        int base = (bid - 97) * 1024 + tid;
        #pragma unroll
        for (int i = 0; i < 4; ++i) {
            int j = base + i * NT;
            dst[j] = src[j & (M_*D_/4 - 1)];
        }
        return;
    }
    if (bid < 96) {
        const int which = bid >> 5;          // 0: tmpq, 1: xg, 2: C
        const int sub   = bid & 31;
        const float* srcA = (which == 2) ? Wv : x;
        int r0 = sub * 8;
        for (int i = tid; i < 2048; i += NT) s_buf[i] = srcA[r0*D_ + i];
        __syncthreads();
        const float* Wcol = (which == 0) ? Wq : (which == 1 ? Wg : (Wg + D_*D_));
        float acc[8];
        #pragma unroll
        for (int r = 0; r < 8; ++r) acc[r] = 0.f;
        #pragma unroll 16
        for (int j = 0; j < D_; ++j) {
            float w = Wcol[j*D_ + tid];
            #pragma unroll
            for (int r = 0; r < 8; ++r) acc[r] += s_buf[r*D_ + j] * w;
        }
        if (which == 0) {
            float bb = bq[tid];
            #pragma unroll
            for (int r = 0; r < 8; ++r) g_tmpq[(r0+r)*D_ + tid] = acc[r] + bb;
        } else if (which == 1) {
            float bb = bg[tid];
            #pragma unroll
            for (int r = 0; r < 8; ++r) g_xg[(r0+r)*D_ + tid] = acc[r] + bb;
        } else {
            #pragma unroll
            for (int r = 0; r < 8; ++r) g_C[(r0+r)*D_ + tid] = acc[r];
        }
    } else {
        g_cnt[tid]      = 0;
        g_cnt[NT + tid] = 0;
        float acc = 0.f;
        #pragma unroll 16
        for (int j = 0; j < D_; ++j) acc += bv[j] * Wg[(D_ + j)*D_ + tid];
        g_bgc[tid] = acc;
    }
}

// ----------------------------- init kernel 2 -----------------------------
// g_qt[bt,d] = (1/sqrt(D)) * sum_k g_tmpq[bt,k] * Wk[d,k]
__global__ void mal_init2(const float* __restrict__ Wk)
{
    __shared__ float s_t[8 * D_];
    const int bid = blockIdx.x, tid = threadIdx.x;
    const int lane = tid & 31, warp = tid >> 5;
    const int r0 = bid * 8;
    for (int i = tid; i < 2048; i += NT) s_t[i] = g_tmpq[r0*D_ + i];
    __syncthreads();

    float4 t0[8], t1[8];
    #pragma unroll
    for (int r = 0; r < 8; ++r) {
        t0[r] = *(const float4*)(s_t + r*D_ + lane*4);
        t1[r] = *(const float4*)(s_t + r*D_ + 128 + lane*4);
    }
    int d = warp * 32;
    float4 w0 = *(const float4*)(Wk + d*D_ + lane*4);
    float4 w1 = *(const float4*)(Wk + d*D_ + 128 + lane*4);
    for (int dd = 0; dd < 32; ++dd) {
        float4 c0 = w0, c1 = w1;
        if (dd < 31) {
            w0 = *(const float4*)(Wk + (d+1)*D_ + lane*4);
            w1 = *(const float4*)(Wk + (d+1)*D_ + 128 + lane*4);
        }
        float dt[8];
        #pragma unroll
        for (int r = 0; r < 8; ++r) {
            dt[r] = t0[r].x*c0.x + t0[r].y*c0.y + t0[r].z*c0.z + t0[r].w*c0.w
                  + t1[r].x*c1.x + t1[r].y*c1.y + t1[r].z*c1.z + t1[r].w*c1.w;
            #pragma unroll
            for (int o = 16; o; o >>= 1) dt[r] += __shfl_xor_sync(0xffffffffu, dt[r], o);
        }
        if (lane == 0) {
            #pragma unroll
            for (int r = 0; r < 8; ++r) g_qt[(r0+r)*D_ + d] = dt[r] * 0.0625f;
        }
        ++d;
    }
}

// ----------------------------- main persistent kernel -----------------------------
__global__ void __launch_bounds__(NT, 1)
mal_main(const float* __restrict__ x, const float* __restrict__ Wv,
         const float* __restrict__ bv, float* __restrict__ out)
{
    __shared__ float s_q[D_];
    __shared__ float s_wacc[8][D_];
    __shared__ float s_lg[128];                   // 128 raw logits
    __shared__ float s_e[128];                    // exp(logit - block max)
    __shared__ float s_r8[8];
    __shared__ float s_cv[128];
    __shared__ int   s_ci[128];
    __shared__ unsigned long long s_pk[128];      // packed (value,index) keys
    __shared__ int   s_rk[NT];                    // split rank counts
    __shared__ int   s_sel[8];                    // global top-8 row ids
    __shared__ float s_p[D_];
    __shared__ float s_red[NT];
    __shared__ float s_scale[16];
    __shared__ float s_bm, s_invS;

    const int tid  = threadIdx.x, lane = tid & 31, warp = tid >> 5;
    const int b    = blockIdx.x >> 4;
    const int blk  = blockIdx.x & 15;
    int* cA        = g_cnt + b * S_;
    int* cB        = g_cnt + NT + b * S_;
    const int d0   = lane * 4;
    const int d1   = 128 + lane * 4;
    const float* baseRow = g_mem + (b*M_ + blk*RPB + warp*16)*D_;

    for (int t = 0; t < S_; ++t) {
        const int buf  = t & 1;
        float* part    = g_part + buf*(B_*GPB*PST) + blockIdx.x * PST;
        int*   tidx    = g_tidx + buf*(B_*GPB*8);

        // ---- apply previous step's gated top-8 updates to owned rows ----
        if (t > 0) {
            bool ownany = false;
            #pragma unroll
            for (int k = 0; k < 8; ++k) if ((s_sel[k] >> 7) == blk) ownany = true;
            if (ownany) {
                if (tid == 0) { while (ldacq(&cB[t-1]) < GPB) { } }
                __syncthreads();
                float gd   = __ldcg(&g_gv[b*D_ + tid]);
                float xd   = __ldg(&x[(b*S_ + (t-1))*D_ + tid]);
                float keep = 1.0f - gd, add = gd * xd;
                #pragma unroll
                for (int k = 0; k < 8; ++k) {
                    int gi = s_sel[k];
                    if ((gi >> 7) == blk) {
                        float* row = g_mem + (b*M_ + gi)*D_;
                        row[tid] = keep * row[tid] + add;
                    }
                }
            }
        }
        s_q[tid] = g_qt[(b*S_ + t)*D_ + tid];
        __syncthreads();

        // ---- pass 1: own 128 rows -> regs, all 128 logits ----
        const float q0 = s_q[d0],   q1 = s_q[d0+1], q2 = s_q[d0+2], q3 = s_q[d0+3];
        const float q4 = s_q[d1],   q5 = s_q[d1+1], q6 = s_q[d1+2], q7 = s_q[d1+3];
        float4 ra[16], rb[16];
        #pragma unroll
        for (int r = 0; r < 16; ++r) {
            ra[r] = *(const float4*)(baseRow + r*D_ + d0);
            rb[r] = *(const float4*)(baseRow + r*D_ + d1);
            float dt = ra[r].x*q0 + ra[r].y*q1 + ra[r].z*q2 + ra[r].w*q3
                     + rb[r].x*q4 + rb[r].y*q5 + rb[r].z*q6 + rb[r].w*q7;
            #pragma unroll
            for (int o = 16; o; o >>= 1) dt += __shfl_xor_sync(0xffffffffu, dt, o);
            if (lane == 0) s_lg[warp*16 + r] = dt;
        }
        __syncthreads();

        // ---- block max, exp table, per-warp sums ----
        float v = (tid < 128) ? s_lg[tid] : NEGINF;
        {
            float m = v;
            #pragma unroll
            for (int o = 16; o; o >>= 1) m = fmaxf(m, __shfl_xor_sync(0xffffffffu, m, o));
            if (lane == 0) s_r8[warp] = m;
        }
        __syncthreads();
        if (tid == 0) {
            float bm = s_r8[0];
            #pragma unroll
            for (int w = 1; w < 8; ++w) bm = fmaxf(bm, s_r8[w]);
            s_bm = bm;
        }
        __syncthreads();
        const float bm = s_bm;
        float e = (tid < 128) ? __expf(v - bm) : 0.f;
        if (tid < 128) s_e[tid] = e;
        {
            float se = e;
            #pragma unroll
            for (int o = 16; o; o >>= 1) se += __shfl_xor_sync(0xffffffffu, se, o);
            if (lane == 0) s_r8[warp] = se;
        }
        // pack local top-8 keys (value desc, tie -> lower index)
        if (tid < 128) {
            unsigned fb = __float_as_uint(v);
            fb ^= (fb & 0x80000000u) ? 0xFFFFFFFFu : 0x80000000u;
            s_pk[tid] = ((unsigned long long)fb << 32) | (unsigned)(~tid);
        }
        __syncthreads();

        // ---- pass 2: weighted row sum from registers + local rank ----
        {
            float4 A = {0,0,0,0}, Bb = {0,0,0,0};
            #pragma unroll
            for (int r = 0; r < 16; ++r) {
                float er = s_e[warp*16 + r];
                A.x += er*ra[r].x; A.y += er*ra[r].y; A.z += er*ra[r].z; A.w += er*ra[r].w;
                Bb.x += er*rb[r].x; Bb.y += er*rb[r].y; Bb.z += er*rb[r].z; Bb.w += er*rb[r].w;
            }
            *(float4*)&s_wacc[warp][d0] = A;
            *(float4*)&s_wacc[warp][d1] = Bb;
        }
        {
            const int c  = tid & 127;
            const int j0 = (tid >> 7) * 64;
            unsigned long long me = s_pk[c];
            int rk = 0;
            #pragma unroll 16
            for (int j = 0; j < 64; ++j) rk += (s_pk[j0 + j] > me);
            s_rk[tid] = rk;
        }
        __syncthreads();
        {
            float pv = 0.f;
            #pragma unroll
            for (int w = 0; w < 8; ++w) pv += s_wacc[w][tid];
            part[2 + tid] = pv;
            if (tid == 0) {
                float sw = 0.f;
                #pragma unroll
                for (int w = 0; w < 8; ++w) sw += s_r8[w];
                part[0] = bm; part[1] = sw;
            }
        }
        if (tid < 128) {
            int rk = s_rk[tid] + s_rk[tid + 128];
            if (rk < 8) {
                part[258 + rk] = s_lg[tid];
                tidx[blockIdx.x*8 + rk] = blk*RPB + tid;
            }
        }
        __syncthreads();
        if (tid == 0) {
            red_release(&cA[t]);
            while (ldacq(&cA[t]) < GPB) { }
        }
        __syncthreads();

        // ---- merge 16 partials (redundant per block) ----
        if (warp == 0) {
            float bmv = (lane < 16) ? __ldcg(&g_part[buf*(B_*GPB*PST) + (b*GPB + lane)*PST])     : NEGINF;
            float swv = (lane < 16) ? __ldcg(&g_part[buf*(B_*GPB*PST) + (b*GPB + lane)*PST + 1]) : 0.f;
            float Mx = bmv;
            #pragma unroll
            for (int o = 16; o; o >>= 1) Mx = fmaxf(Mx, __shfl_xor_sync(0xffffffffu, Mx, o));
            float sc = (lane < 16) ? __expf(bmv - Mx) : 0.f;
            if (lane < 16) s_scale[lane] = sc;
            float Ssum = sc * swv;
            #pragma unroll
            for (int o = 16; o; o >>= 1) Ssum += __shfl_xor_sync(0xffffffffu, Ssum, o);
            if (lane == 0) s_invS = 1.0f / Ssum;
        } else if (warp >= 4) {
            int ii = tid - 128;
            int i = ii >> 3, j = ii & 7;
            s_cv[ii] = __ldcg(&g_part[buf*(B_*GPB*PST) + (b*GPB + i)*PST + 258 + j]);
            s_ci[ii] = __ldcg(&g_tidx[buf*(B_*GPB*8) + (b*GPB + i)*8 + j]);
        }
        __syncthreads();
        {
            float pv = 0.f;
            #pragma unroll
            for (int i = 0; i < 16; ++i)
                pv += __ldcg(&g_part[buf*(B_*GPB*PST) + (b*GPB + i)*PST + 2 + tid]) * s_scale[i];
            s_p[tid] = pv * s_invS;
        }
        if (tid < 128) {
            unsigned fb = __float_as_uint(s_cv[tid]);
            fb ^= (fb & 0x80000000u) ? 0xFFFFFFFFu : 0x80000000u;
            s_pk[tid] = ((unsigned long long)fb << 32) | (unsigned)(~s_ci[tid]);
        }
        __syncthreads();

        // ---- global top-8 rank (overlapped with slice GEMV LDGs) ----
        {
            const int c  = tid & 127;
            const int j0 = (tid >> 7) * 64;
            unsigned long long me = s_pk[c];
            int rk = 0;
            #pragma unroll 16
            for (int j = 0; j < 64; ++j) rk += (s_pk[j0 + j] > me);
            s_rk[tid] = rk;
        }
        {
            const int dbase = blk * 16;
            const float* Mp = (lane < 16) ? (Wv + dbase + lane)
                                          : (g_C + dbase + (lane - 16));
            float acc = 0.f;
            const int k0 = warp * 32;
            #pragma unroll
            for (int kk = 0; kk < 32; ++kk)
                acc += s_p[k0 + kk] * Mp[(k0 + kk)*D_];
            s_red[tid] = acc;
        }
        __syncthreads();
        if (tid < 128) {
            int rk = s_rk[tid] + s_rk[tid + 128];
            if (rk < 8) s_sel[rk] = s_ci[tid];
        }
        if (tid < 32) {
            float tot = 0.f;
            #pragma unroll
            for (int w = 0; w < 8; ++w) tot += s_red[w*32 + tid];
            const int dbase = blk * 16;
            if (tid < 16) {
                out[(b*S_ + t)*D_ + dbase + tid] = tot + __ldg(&bv[dbase + tid]);
            } else {
                int d = dbase + tid - 16;
                float z = g_xg[(b*S_ + t)*D_ + d] + g_bgc[d] + tot;
                g_gv[b*D_ + d] = 1.0f / (1.0f + __expf(-z));
            }
        }
        __syncthreads();
        if (tid == 0) red_release(&cB[t]);    // owners wait at t+1
    }
}

// ----------------------------- launch -----------------------------
extern "C" void kernel_launch(void* const* d_in, const int* in_sizes, int n_in,
                              void* d_out, int out_size)
{
    const float* x      = (const float*)d_in[0];
    const float* memory = (const float*)d_in[1];
    const float* Wq     = (const float*)d_in[2];
    const float* bq     = (const float*)d_in[3];
    const float* Wk     = (const float*)d_in[4];
    // d_in[5] = bk : constant logit shift; softmax/top-k invariant -> unused
    const float* Wv     = (const float*)d_in[6];
    const float* bv     = (const float*)d_in[7];
    const float* Wg     = (const float*)d_in[8];
    const float* bg     = (const float*)d_in[9];
    float* out = (float*)d_out;

    mal_init1<<<1121, NT>>>(x, memory, Wq, bq, Wg, bg, Wv, bv);
    mal_init2<<<32, NT>>>(Wk);
    mal_main<<<B_*GPB, NT>>>(x, Wv, bv, out);
}